// round 4
// baseline (speedup 1.0000x reference)
#include <cuda_runtime.h>
#include <cuda_bf16.h>
#include <cstdint>

// Fixed shapes for NEG_loss_44461501448871
#define EMB    256
#define BSZ    4096
#define WSZ    5
#define SSZ    15
#define NPAIR  (BSZ * WSZ)        // 20480
#define WARPS_PER_BLOCK 8
#define NBLOCKS (NPAIR / WARPS_PER_BLOCK)  // 2560
#define FULLM  0xFFFFFFFFu

__device__ float g_block_partials[NBLOCKS];
__device__ unsigned int g_done_count;  // zero-init; last block resets

__device__ __forceinline__ float log_sigmoid_f(float x) {
    // log(sigmoid(x)) = min(x,0) - log(1 + exp(-|x|)); fast-math MUFU path.
    return fminf(x, 0.0f) - __logf(1.0f + __expf(-fabsf(x)));
}

__device__ __forceinline__ float dot8(const float4& a0, const float4& a1,
                                      const float4& b0, const float4& b1) {
    float d;
    d  = a0.x * b0.x;
    d  = fmaf(a0.y, b0.y, d);
    d  = fmaf(a0.z, b0.z, d);
    d  = fmaf(a0.w, b0.w, d);
    d  = fmaf(a1.x, b1.x, d);
    d  = fmaf(a1.y, b1.y, d);
    d  = fmaf(a1.z, b1.z, d);
    d  = fmaf(a1.w, b1.w, d);
    return d;
}

__device__ __forceinline__ float warp_sum(float v) {
    #pragma unroll
    for (int m = 16; m > 0; m >>= 1)
        v += __shfl_xor_sync(FULLM, v, m);
    return v;
}

// One warp per (b,w) pair; 16 gathered rows per pair; 4-row groups reduced by
// a value-exchanging butterfly. __launch_bounds__(256,8) caps regs at 32 so
// 64 warps/SM can overlap the L2-latency-dominated gathers.
__global__ __launch_bounds__(256, 8) void neg_fused_kernel(
    const float* __restrict__ in_w,
    const float* __restrict__ out_w,
    const int*   __restrict__ in_lab,     // [B]
    const int*   __restrict__ out_lab,    // [B*W]
    const int*   __restrict__ noise_lab,  // [B*W, S]
    float*       __restrict__ out)
{
    __shared__ float sm_warp[WARPS_PER_BLOCK];
    const int lane = threadIdx.x & 31;
    const int wib  = threadIdx.x >> 5;
    const int n    = blockIdx.x * WARPS_PER_BLOCK + wib;  // pair id < NPAIR

    const int in_idx  = __ldg(&in_lab[n & (BSZ - 1)]);   // tile(input_labels, W)
    const int out_idx = __ldg(&out_lab[n]);

    const float4* inp4 = reinterpret_cast<const float4*>(in_w + (size_t)in_idx * EMB);
    const float4 a0 = __ldg(&inp4[lane]);
    const float4 a1 = __ldg(&inp4[lane + 32]);

    // Noise labels spread across lanes; broadcast by shfl at use.
    const int* nl = noise_lab + (size_t)n * SSZ;
    int my_idx = (lane < SSZ) ? __ldg(&nl[lane]) : 0;

    const bool sel16 = (lane & 16) != 0;
    const bool sel8  = (lane & 8) != 0;

    float acc = 0.0f;
    #pragma unroll
    for (int g = 0; g < 4; g++) {
        // Row dots for this group (noise rows sign-folded: reference negates noise)
        float q[4];
        #pragma unroll
        for (int j = 0; j < 4; j++) {
            const int r = g * 4 + j;
            const int idx = (r == 0) ? out_idx : __shfl_sync(FULLM, my_idx, r - 1);
            const float4* r4 = reinterpret_cast<const float4*>(out_w + (size_t)idx * EMB);
            const float d = dot8(a0, a1, __ldg(&r4[lane]), __ldg(&r4[lane + 32]));
            q[j] = (r == 0) ? d : -d;
        }
        // Butterfly: 4 independent 32-lane sums in 6 shfl; each sum ends on 8 lanes.
        float s0 = sel16 ? q[0] : q[2];
        float s1 = sel16 ? q[1] : q[3];
        float r0 = __shfl_xor_sync(FULLM, s0, 16);
        float r1 = __shfl_xor_sync(FULLM, s1, 16);
        float t0 = (sel16 ? q[2] : q[0]) + r0;
        float t1 = (sel16 ? q[3] : q[1]) + r1;
        float s2 = sel8 ? t0 : t1;
        float r2 = __shfl_xor_sync(FULLM, s2, 8);
        float u  = (sel8 ? t1 : t0) + r2;
        u += __shfl_xor_sync(FULLM, u, 4);
        u += __shfl_xor_sync(FULLM, u, 2);
        u += __shfl_xor_sync(FULLM, u, 1);
        // u = full dot for one of the 4 rows (replicated x8 lanes)
        acc += log_sigmoid_f(u);
    }

    // Each row's logsig counted on 8 lanes -> scale by 1/8.
    const float pair_loss = warp_sum(acc) * 0.125f;

    // Block reduce (fixed order -> deterministic)
    if (lane == 0) sm_warp[wib] = pair_loss;
    __syncthreads();

    if (threadIdx.x == 0) {
        float b = sm_warp[0];
        #pragma unroll
        for (int w = 1; w < WARPS_PER_BLOCK; w++) b += sm_warp[w];
        g_block_partials[blockIdx.x] = b;
        __threadfence();
    }
    __syncthreads();

    // Last-block grid reduction (fixed order)
    __shared__ unsigned int s_ticket;
    if (threadIdx.x == 0)
        s_ticket = atomicAdd(&g_done_count, 1u);
    __syncthreads();

    if (s_ticket == NBLOCKS - 1) {
        float s = 0.0f;
        #pragma unroll
        for (int i = 0; i < NBLOCKS / 256; i++)
            s += g_block_partials[threadIdx.x + i * 256];
        s = warp_sum(s);
        if (lane == 0) sm_warp[wib] = s;
        __syncthreads();
        if (threadIdx.x == 0) {
            float t = sm_warp[0];
            #pragma unroll
            for (int w = 1; w < WARPS_PER_BLOCK; w++) t += sm_warp[w];
            out[0] = -t / (float)BSZ;
            g_done_count = 0;  // reset for next graph replay
        }
    }
}

extern "C" void kernel_launch(void* const* d_in, const int* in_sizes, int n_in,
                              void* d_out, int out_size) {
    const float* in_w      = (const float*)d_in[0];   // [V, E]
    const float* out_w     = (const float*)d_in[1];   // [V, E]
    const int*   in_lab    = (const int*)d_in[2];     // [B]
    const int*   out_lab   = (const int*)d_in[3];     // [B, W]
    const int*   noise_lab = (const int*)d_in[4];     // [B*W, S]
    (void)in_sizes; (void)n_in; (void)out_size;

    neg_fused_kernel<<<NBLOCKS, 256>>>(in_w, out_w, in_lab, out_lab, noise_lab,
                                       (float*)d_out);
}

// round 5
// speedup vs baseline: 1.2424x; 1.2424x over previous
#include <cuda_runtime.h>
#include <cuda_bf16.h>
#include <cstdint>

// Fixed shapes for NEG_loss_44461501448871
#define EMB    256
#define BSZ    4096
#define WSZ    5
#define SSZ    15
#define NPAIR  (BSZ * WSZ)        // 20480
#define WARPS_PER_BLOCK 8
#define NBLOCKS (BSZ / WARPS_PER_BLOCK)  // 512 (warp per input label)
#define FULLM  0xFFFFFFFFu

__device__ float g_block_partials[NBLOCKS];
__device__ unsigned int g_done_count;  // zero-init; last block resets

__device__ __forceinline__ float log_sigmoid_f(float x) {
    // log(sigmoid(x)) = min(x,0) - log(1 + exp(-|x|)); fast-math MUFU path.
    return fminf(x, 0.0f) - __logf(1.0f + __expf(-fabsf(x)));
}

__device__ __forceinline__ float dot8(const float4& a0, const float4& a1,
                                      const float4& b0, const float4& b1) {
    float d;
    d  = a0.x * b0.x;
    d  = fmaf(a0.y, b0.y, d);
    d  = fmaf(a0.z, b0.z, d);
    d  = fmaf(a0.w, b0.w, d);
    d  = fmaf(a1.x, b1.x, d);
    d  = fmaf(a1.y, b1.y, d);
    d  = fmaf(a1.z, b1.z, d);
    d  = fmaf(a1.w, b1.w, d);
    return d;
}

__device__ __forceinline__ float warp_sum(float v) {
    #pragma unroll
    for (int m = 16; m > 0; m >>= 1)
        v += __shfl_xor_sync(FULLM, v, m);
    return v;
}

// Warp r handles the 5 pairs n = r + k*BSZ (k=0..4), which share
// inp row in_embed[input_labels[r]] -> loaded ONCE into registers.
// Per pair: 16 gathered out-rows, reduced in 4-row groups via a
// value-exchanging butterfly; one log-sigmoid per lane per group.
__global__ __launch_bounds__(256) void neg_fused_kernel(
    const float* __restrict__ in_w,
    const float* __restrict__ out_w,
    const int*   __restrict__ in_lab,     // [B]
    const int*   __restrict__ out_lab,    // [B*W] flat
    const int*   __restrict__ noise_lab,  // [B*W, S]
    float*       __restrict__ out)
{
    __shared__ float sm_warp[WARPS_PER_BLOCK];
    const int lane = threadIdx.x & 31;
    const int wib  = threadIdx.x >> 5;
    const int r    = blockIdx.x * WARPS_PER_BLOCK + wib;  // input-label id < BSZ

    const int in_idx = __ldg(&in_lab[r]);
    const float4* inp4 = reinterpret_cast<const float4*>(in_w + (size_t)in_idx * EMB);
    const float4 a0 = __ldg(&inp4[lane]);
    const float4 a1 = __ldg(&inp4[lane + 32]);

    const bool sel16 = (lane & 16) != 0;
    const bool sel8  = (lane & 8) != 0;

    float acc = 0.0f;  // sum of log-sigmoids; each counted on 8 lanes

    #pragma unroll
    for (int k = 0; k < WSZ; k++) {
        const int n = r + k * BSZ;            // pair id (reshape(-1) order: n % B = r)
        const int out_idx = __ldg(&out_lab[n]);
        const int* nl = noise_lab + (size_t)n * SSZ;
        const int my_idx = (lane < SSZ) ? __ldg(&nl[lane]) : 0;

        #pragma unroll
        for (int g = 0; g < 4; g++) {
            // Row dots for this group (noise rows sign-folded)
            float q[4];
            #pragma unroll
            for (int j = 0; j < 4; j++) {
                const int rr = g * 4 + j;
                const int idx = (rr == 0) ? out_idx
                                          : __shfl_sync(FULLM, my_idx, rr - 1);
                const float4* r4 =
                    reinterpret_cast<const float4*>(out_w + (size_t)idx * EMB);
                const float d = dot8(a0, a1, __ldg(&r4[lane]), __ldg(&r4[lane + 32]));
                q[j] = (rr == 0) ? d : -d;
            }
            // Butterfly: 4 independent 32-lane sums in 6 shfl; result x8 lanes.
            float s0 = sel16 ? q[0] : q[2];
            float s1 = sel16 ? q[1] : q[3];
            float r0 = __shfl_xor_sync(FULLM, s0, 16);
            float r1 = __shfl_xor_sync(FULLM, s1, 16);
            float t0 = (sel16 ? q[2] : q[0]) + r0;
            float t1 = (sel16 ? q[3] : q[1]) + r1;
            float s2 = sel8 ? t0 : t1;
            float r2 = __shfl_xor_sync(FULLM, s2, 8);
            float u  = (sel8 ? t1 : t0) + r2;
            u += __shfl_xor_sync(FULLM, u, 4);
            u += __shfl_xor_sync(FULLM, u, 2);
            u += __shfl_xor_sync(FULLM, u, 1);
            acc += log_sigmoid_f(u);
        }
    }

    // Each logsig counted on 8 lanes -> scale by 1/8 after the warp sum.
    const float warp_loss = warp_sum(acc) * 0.125f;

    // Block reduce (fixed order -> deterministic)
    if (lane == 0) sm_warp[wib] = warp_loss;
    __syncthreads();

    if (threadIdx.x == 0) {
        float b = sm_warp[0];
        #pragma unroll
        for (int w = 1; w < WARPS_PER_BLOCK; w++) b += sm_warp[w];
        g_block_partials[blockIdx.x] = b;
        __threadfence();
    }
    __syncthreads();

    // Last-block grid reduction (fixed order)
    __shared__ unsigned int s_ticket;
    if (threadIdx.x == 0)
        s_ticket = atomicAdd(&g_done_count, 1u);
    __syncthreads();

    if (s_ticket == NBLOCKS - 1) {
        float s = 0.0f;
        #pragma unroll
        for (int i = 0; i < NBLOCKS / 256; i++)
            s += g_block_partials[threadIdx.x + i * 256];
        s = warp_sum(s);
        if (lane == 0) sm_warp[wib] = s;
        __syncthreads();
        if (threadIdx.x == 0) {
            float t = sm_warp[0];
            #pragma unroll
            for (int w = 1; w < WARPS_PER_BLOCK; w++) t += sm_warp[w];
            out[0] = -t / (float)BSZ;
            g_done_count = 0;  // reset for next graph replay
        }
    }
}

extern "C" void kernel_launch(void* const* d_in, const int* in_sizes, int n_in,
                              void* d_out, int out_size) {
    const float* in_w      = (const float*)d_in[0];   // [V, E]
    const float* out_w     = (const float*)d_in[1];   // [V, E]
    const int*   in_lab    = (const int*)d_in[2];     // [B]
    const int*   out_lab   = (const int*)d_in[3];     // [B, W]
    const int*   noise_lab = (const int*)d_in[4];     // [B*W, S]
    (void)in_sizes; (void)n_in; (void)out_size;

    neg_fused_kernel<<<NBLOCKS, 256>>>(in_w, out_w, in_lab, out_lab, noise_lab,
                                       (float*)d_out);
}